// round 1
// baseline (speedup 1.0000x reference)
#include <cuda_runtime.h>

#define NN 200000
#define EE 6400000
#define FF 128
#define HH 16
#define CC 40
#define NBLK 196   // ceil(NN/1024)

// ---------------- device scratch (static, no runtime allocation) -------------
__device__ int    g_is64;
__device__ int    d_cnt[NN];
__device__ int    d_rowptr[NN];
__device__ int    d_cursor[NN];
__device__ int    d_bsum[NBLK];
__device__ float  d_dis[NN];
__device__ float  d_dis2[NN];
__device__ float2 d_csr[EE];          // {src (int bits), norm}
__device__ float  d_bufA[NN * HH];    // premultiplied features hw
__device__ float  d_bufB[NN * HH];    // aggregation accumulator

// ---------------- prep kernels ----------------------------------------------

__global__ void k_init() {
    int i = blockIdx.x * blockDim.x + threadIdx.x;
    if (i < NN) d_cnt[i] = 0;
    if (i == 0) g_is64 = 1;
}

// edge_index values are in [0, 200000) >= 0. If the buffer is int64
// (little-endian), every odd 32-bit word is 0. If int32, odd words are random
// node ids — essentially never all zero over 1024 samples.
__global__ void k_detect(const int* __restrict__ ei) {
    int i = threadIdx.x;                  // 1024 threads, 1 block
    if (ei[2 * i + 1] != 0) g_is64 = 0;
}

__global__ void k_count(const void* __restrict__ ei) {
    int e = blockIdx.x * blockDim.x + threadIdx.x;
    if (e >= EE) return;
    int d;
    if (g_is64) d = (int)((const long long*)ei)[(long long)EE + e];
    else        d = ((const int*)ei)[EE + e];
    atomicAdd(&d_cnt[d], 1);
}

__global__ void k_dis() {
    int i = blockIdx.x * blockDim.x + threadIdx.x;
    if (i >= NN) return;
    int c = d_cnt[i] + 1;                 // + self loop
    d_dis[i]  = rsqrtf((float)c);
    d_dis2[i] = 1.0f / (float)c;
}

// exclusive scan of d_cnt -> d_rowptr (3 kernels)
__global__ void k_scan1() {
    __shared__ int sh[1024];
    int tid = threadIdx.x;
    int i = blockIdx.x * 1024 + tid;
    int v = (i < NN) ? d_cnt[i] : 0;
    sh[tid] = v;
    __syncthreads();
    for (int off = 1; off < 1024; off <<= 1) {
        int t = 0;
        if (tid >= off) t = sh[tid - off];
        __syncthreads();
        sh[tid] += t;
        __syncthreads();
    }
    if (i < NN) d_rowptr[i] = sh[tid] - v;  // exclusive
    if (tid == 1023) d_bsum[blockIdx.x] = sh[1023];
}

__global__ void k_scan2() {
    if (threadIdx.x == 0) {
        int acc = 0;
        for (int b = 0; b < NBLK; b++) {
            int t = d_bsum[b];
            d_bsum[b] = acc;
            acc += t;
        }
    }
}

__global__ void k_scan3() {
    int i = blockIdx.x * blockDim.x + threadIdx.x;
    if (i >= NN) return;
    int r = d_rowptr[i] + d_bsum[i >> 10];
    d_rowptr[i] = r;
    d_cursor[i] = r;
}

__global__ void k_scatter(const void* __restrict__ ei) {
    int e = blockIdx.x * blockDim.x + threadIdx.x;
    if (e >= EE) return;
    int s, d;
    if (g_is64) {
        s = (int)((const long long*)ei)[e];
        d = (int)((const long long*)ei)[(long long)EE + e];
    } else {
        s = ((const int*)ei)[e];
        d = ((const int*)ei)[EE + e];
    }
    int pos = atomicAdd(&d_cursor[d], 1);
    d_csr[pos] = make_float2(__int_as_float(s), d_dis[s] * d_dis[d]);
}

// ---------------- dense kernels ----------------------------------------------

// hw = X @ W_in; acc = hw * dis2 (self-loop preinit). 256 nodes/block,
// k-tiled shared X, thread = (4 nodes) x (4 output cols).
__global__ __launch_bounds__(256) void k_xw(const float* __restrict__ x,
                                            const float* __restrict__ w,
                                            float* __restrict__ hw,
                                            float* __restrict__ acc) {
    __shared__ float  xs[256 * 33];
    __shared__ float4 ws4[FF * 4];      // 128x16 floats
    int tid = threadIdx.x;
    int base = blockIdx.x * 256;

    const float4* wv = (const float4*)w;
    for (int i = tid; i < FF * 4; i += 256) ws4[i] = wv[i];

    int cg = tid & 3;                    // output col group (4 cols)
    int g  = tid >> 2;                   // node group, 4 nodes each
    float4 o[4];
    #pragma unroll
    for (int i = 0; i < 4; i++) o[i] = make_float4(0.f, 0.f, 0.f, 0.f);

    for (int kc = 0; kc < 4; kc++) {     // k tiles of 32
        __syncthreads();
        for (int i = tid; i < 256 * 32; i += 256) {
            int r = i >> 5, c = i & 31;
            int n = base + r;
            xs[r * 33 + c] = (n < NN) ? x[n * FF + kc * 32 + c] : 0.f;
        }
        __syncthreads();
        #pragma unroll
        for (int kk = 0; kk < 32; kk++) {
            int k = kc * 32 + kk;
            float4 w4 = ws4[k * 4 + cg];
            #pragma unroll
            for (int i = 0; i < 4; i++) {
                float xv = xs[(g * 4 + i) * 33 + kk];
                o[i].x = fmaf(xv, w4.x, o[i].x);
                o[i].y = fmaf(xv, w4.y, o[i].y);
                o[i].z = fmaf(xv, w4.z, o[i].z);
                o[i].w = fmaf(xv, w4.w, o[i].w);
            }
        }
    }
    #pragma unroll
    for (int i = 0; i < 4; i++) {
        int n = base + g * 4 + i;
        if (n < NN) {
            ((float4*)hw)[n * 4 + cg] = o[i];
            float s2 = d_dis2[n];
            float4 a = make_float4(o[i].x * s2, o[i].y * s2, o[i].z * s2, o[i].w * s2);
            ((float4*)acc)[n * 4 + cg] = a;
        }
    }
}

// h = relu(agg + bias); hw = h @ W (16x16); acc = hw * dis2.
// agg may alias acc (per-thread, same-element read-then-write).
__global__ __launch_bounds__(256) void k_transform(const float* __restrict__ agg,
                                                   const float* __restrict__ bias,
                                                   const float* __restrict__ W,
                                                   float* __restrict__ hw,
                                                   float* __restrict__ acc) {
    __shared__ float4 ws4[64];
    __shared__ float  bs[16];
    int tid = threadIdx.x;
    if (tid < 64) ws4[tid] = ((const float4*)W)[tid];
    if (tid < 16) bs[tid] = bias[tid];
    __syncthreads();

    int n = blockIdx.x * 256 + tid;
    if (n >= NN) return;

    float h[16];
    const float4* av = (const float4*)agg;
    #pragma unroll
    for (int q = 0; q < 4; q++) {
        float4 a = av[n * 4 + q];
        h[q * 4 + 0] = fmaxf(a.x + bs[q * 4 + 0], 0.f);
        h[q * 4 + 1] = fmaxf(a.y + bs[q * 4 + 1], 0.f);
        h[q * 4 + 2] = fmaxf(a.z + bs[q * 4 + 2], 0.f);
        h[q * 4 + 3] = fmaxf(a.w + bs[q * 4 + 3], 0.f);
    }
    float4 o[4];
    #pragma unroll
    for (int q = 0; q < 4; q++) o[q] = make_float4(0.f, 0.f, 0.f, 0.f);
    #pragma unroll
    for (int k = 0; k < 16; k++) {
        float hk = h[k];
        #pragma unroll
        for (int q = 0; q < 4; q++) {
            float4 w4 = ws4[k * 4 + q];
            o[q].x = fmaf(hk, w4.x, o[q].x);
            o[q].y = fmaf(hk, w4.y, o[q].y);
            o[q].z = fmaf(hk, w4.z, o[q].z);
            o[q].w = fmaf(hk, w4.w, o[q].w);
        }
    }
    float s2 = d_dis2[n];
    #pragma unroll
    for (int q = 0; q < 4; q++) {
        ((float4*)hw)[n * 4 + q] = o[q];
        float4 a = make_float4(o[q].x * s2, o[q].y * s2, o[q].z * s2, o[q].w * s2);
        ((float4*)acc)[n * 4 + q] = a;
    }
}

// hw = relu(agg + bias) (identity weights, before the output-layer SpMM)
__global__ __launch_bounds__(256) void k_relu_scale(const float* __restrict__ agg,
                                                    const float* __restrict__ bias,
                                                    float* __restrict__ hw,
                                                    float* __restrict__ acc) {
    __shared__ float bs[16];
    int tid = threadIdx.x;
    if (tid < 16) bs[tid] = bias[tid];
    __syncthreads();
    int n = blockIdx.x * 256 + tid;
    if (n >= NN) return;
    float s2 = d_dis2[n];
    const float4* av = (const float4*)agg;
    #pragma unroll
    for (int q = 0; q < 4; q++) {
        float4 a = av[n * 4 + q];
        float4 hq;
        hq.x = fmaxf(a.x + bs[q * 4 + 0], 0.f);
        hq.y = fmaxf(a.y + bs[q * 4 + 1], 0.f);
        hq.z = fmaxf(a.z + bs[q * 4 + 2], 0.f);
        hq.w = fmaxf(a.w + bs[q * 4 + 3], 0.f);
        ((float4*)hw)[n * 4 + q] = hq;
        float4 ac = make_float4(hq.x * s2, hq.y * s2, hq.z * s2, hq.w * s2);
        ((float4*)acc)[n * 4 + q] = ac;
    }
}

// ---------------- SpMM: out[n] (preinit with self term) += sum norm*hw[src] --
__global__ __launch_bounds__(256) void k_spmm(const float* __restrict__ hw,
                                              float* __restrict__ out) {
    int n = blockIdx.x * 256 + threadIdx.x;
    if (n >= NN) return;
    int start = d_rowptr[n];
    int end   = start + d_cnt[n];
    const float4* hv = (const float4*)hw;
    float4* ov = (float4*)out;
    float4 a0 = ov[n * 4 + 0];
    float4 a1 = ov[n * 4 + 1];
    float4 a2 = ov[n * 4 + 2];
    float4 a3 = ov[n * 4 + 3];
    for (int j = start; j < end; j++) {
        float2 p = d_csr[j];
        int   s  = __float_as_int(p.x);
        float nr = p.y;
        float4 v0 = __ldg(hv + s * 4 + 0);
        float4 v1 = __ldg(hv + s * 4 + 1);
        float4 v2 = __ldg(hv + s * 4 + 2);
        float4 v3 = __ldg(hv + s * 4 + 3);
        a0.x = fmaf(nr, v0.x, a0.x); a0.y = fmaf(nr, v0.y, a0.y);
        a0.z = fmaf(nr, v0.z, a0.z); a0.w = fmaf(nr, v0.w, a0.w);
        a1.x = fmaf(nr, v1.x, a1.x); a1.y = fmaf(nr, v1.y, a1.y);
        a1.z = fmaf(nr, v1.z, a1.z); a1.w = fmaf(nr, v1.w, a1.w);
        a2.x = fmaf(nr, v2.x, a2.x); a2.y = fmaf(nr, v2.y, a2.y);
        a2.z = fmaf(nr, v2.z, a2.z); a2.w = fmaf(nr, v2.w, a2.w);
        a3.x = fmaf(nr, v3.x, a3.x); a3.y = fmaf(nr, v3.y, a3.y);
        a3.z = fmaf(nr, v3.z, a3.z); a3.w = fmaf(nr, v3.w, a3.w);
    }
    ov[n * 4 + 0] = a0;
    ov[n * 4 + 1] = a1;
    ov[n * 4 + 2] = a2;
    ov[n * 4 + 3] = a3;
}

// ---------------- output: z = agg @ W_out + b_out, log_softmax ---------------
__global__ __launch_bounds__(256) void k_out(const float* __restrict__ agg,
                                             const float* __restrict__ W,
                                             const float* __restrict__ bias,
                                             float* __restrict__ out) {
    __shared__ float4 wo4[HH * 10];      // 16 x 40 floats
    __shared__ float4 bo4[10];
    int tid = threadIdx.x;
    if (tid < HH * 10) wo4[tid] = ((const float4*)W)[tid];
    if (tid < 10) bo4[tid] = ((const float4*)bias)[tid];
    __syncthreads();

    int n = blockIdx.x * 256 + tid;
    if (n >= NN) return;

    float t[16];
    const float4* av = (const float4*)agg;
    #pragma unroll
    for (int q = 0; q < 4; q++) {
        float4 a = av[n * 4 + q];
        t[q * 4 + 0] = a.x; t[q * 4 + 1] = a.y;
        t[q * 4 + 2] = a.z; t[q * 4 + 3] = a.w;
    }
    float4 z[10];
    #pragma unroll
    for (int j = 0; j < 10; j++) z[j] = bo4[j];
    #pragma unroll
    for (int k = 0; k < 16; k++) {
        float tk = t[k];
        #pragma unroll
        for (int j = 0; j < 10; j++) {
            float4 w4 = wo4[k * 10 + j];
            z[j].x = fmaf(tk, w4.x, z[j].x);
            z[j].y = fmaf(tk, w4.y, z[j].y);
            z[j].z = fmaf(tk, w4.z, z[j].z);
            z[j].w = fmaf(tk, w4.w, z[j].w);
        }
    }
    float m = -1e30f;
    #pragma unroll
    for (int j = 0; j < 10; j++) {
        m = fmaxf(m, fmaxf(fmaxf(z[j].x, z[j].y), fmaxf(z[j].z, z[j].w)));
    }
    float ssum = 0.f;
    #pragma unroll
    for (int j = 0; j < 10; j++) {
        ssum += __expf(z[j].x - m) + __expf(z[j].y - m) +
                __expf(z[j].z - m) + __expf(z[j].w - m);
    }
    float lse = m + logf(ssum);
    float4* ov = (float4*)out;
    #pragma unroll
    for (int j = 0; j < 10; j++) {
        float4 r = make_float4(z[j].x - lse, z[j].y - lse, z[j].z - lse, z[j].w - lse);
        ov[n * 10 + j] = r;
    }
}

// ---------------- launch ------------------------------------------------------

extern "C" void kernel_launch(void* const* d_in, const int* in_sizes, int n_in,
                              void* d_out, int out_size) {
    const float* x     = (const float*)d_in[0];
    const float* w_in  = (const float*)d_in[1];
    const float* b_in  = (const float*)d_in[2];
    const float* w_hid = (const float*)d_in[3];
    const float* b_hid = (const float*)d_in[4];
    const float* w_out = (const float*)d_in[5];
    const float* b_out = (const float*)d_in[6];
    const void*  ei    = d_in[7];
    float* outp = (float*)d_out;

    float* bufA; cudaGetSymbolAddress((void**)&bufA, d_bufA);
    float* bufB; cudaGetSymbolAddress((void**)&bufB, d_bufB);

    const int GB_N = (NN + 255) / 256;
    const int GB_E = (EE + 255) / 256;

    // prep: dtype detect, degree, dis, scan, scatter (dst-sorted CSR)
    k_init<<<GB_N, 256>>>();
    k_detect<<<1, 1024>>>((const int*)ei);
    k_count<<<GB_E, 256>>>(ei);
    k_dis<<<GB_N, 256>>>();
    k_scan1<<<NBLK, 1024>>>();
    k_scan2<<<1, 32>>>();
    k_scan3<<<GB_N, 256>>>();
    k_scatter<<<GB_E, 256>>>(ei);

    // layer 0: hw = X @ W_in, acc preinit with self term, then aggregate
    k_xw<<<(NN + 255) / 256, 256>>>(x, w_in, bufA, bufB);
    k_spmm<<<GB_N, 256>>>(bufA, bufB);

    // 8 hidden layers: relu(agg+b_prev) @ W_i, aggregate
    for (int i = 0; i < 8; i++) {
        const float* bias = (i == 0) ? b_in : (b_hid + (i - 1) * HH);
        const float* W    = w_hid + i * HH * HH;
        k_transform<<<GB_N, 256>>>(bufB, bias, W, bufA, bufB);
        k_spmm<<<GB_N, 256>>>(bufA, bufB);
    }

    // output layer: aggregate first (16-wide), then @ W_out + b_out + logsoftmax
    k_relu_scale<<<GB_N, 256>>>(bufB, b_hid + 7 * HH, bufA, bufB);
    k_spmm<<<GB_N, 256>>>(bufA, bufB);
    k_out<<<GB_N, 256>>>(bufB, w_out, b_out, outp);
}

// round 2
// speedup vs baseline: 1.8032x; 1.8032x over previous
#include <cuda_runtime.h>

#define NN 200000
#define EE 6400000
#define FF 128
#define HH 16
#define NBLK 196   // ceil(NN/1024)

// ---------------- device scratch -------------------------------------------
__device__ int    g_is64;
__device__ int    d_cnt[NN];
__device__ int    d_rowptr[NN];
__device__ int    d_cursor[NN];
__device__ int    d_bsum[NBLK];
__device__ float  d_dis[NN];
__device__ float  d_dis2[NN];
__device__ float2 d_csr[EE];          // {src (int bits), norm}
__device__ float4 d_bufA[NN * 4];
__device__ float4 d_bufB[NN * 4];
__device__ float4 d_bufC[NN * 4];

// ---------------- prep -------------------------------------------------------

// zero counters + int64/int32 detection (block 0 samples 256 odd words)
__global__ void k_init(const int* __restrict__ ei) {
    int i = blockIdx.x * blockDim.x + threadIdx.x;
    if (i < NN) d_cnt[i] = 0;
    if (blockIdx.x == 0) {
        if (threadIdx.x == 0) g_is64 = 1;
        __syncthreads();
        if (ei[2 * threadIdx.x + 1] != 0) g_is64 = 0;
    }
}

__global__ void k_count(const void* __restrict__ ei) {
    int e = blockIdx.x * blockDim.x + threadIdx.x;
    if (e >= EE) return;
    int d;
    if (g_is64) d = (int)((const long long*)ei)[(long long)EE + e];
    else        d = ((const int*)ei)[EE + e];
    atomicAdd(&d_cnt[d], 1);
}

// block scan of cnt (exclusive) + fused dis/dis2 computation
__global__ void k_scan1() {
    __shared__ int sh[1024];
    int tid = threadIdx.x;
    int i = blockIdx.x * 1024 + tid;
    int v = (i < NN) ? d_cnt[i] : 0;
    if (i < NN) {
        float r = rsqrtf((float)(v + 1));
        d_dis[i]  = r;
        d_dis2[i] = r * r;
    }
    sh[tid] = v;
    __syncthreads();
    for (int off = 1; off < 1024; off <<= 1) {
        int t = 0;
        if (tid >= off) t = sh[tid - off];
        __syncthreads();
        sh[tid] += t;
        __syncthreads();
    }
    if (i < NN) d_rowptr[i] = sh[tid] - v;
    if (tid == 1023) d_bsum[blockIdx.x] = sh[1023];
}

__global__ void k_scan2() {
    if (threadIdx.x == 0) {
        int acc = 0;
        for (int b = 0; b < NBLK; b++) {
            int t = d_bsum[b];
            d_bsum[b] = acc;
            acc += t;
        }
    }
}

__global__ void k_scan3() {
    int i = blockIdx.x * blockDim.x + threadIdx.x;
    if (i >= NN) return;
    int r = d_rowptr[i] + d_bsum[i >> 10];
    d_rowptr[i] = r;
    d_cursor[i] = r;
}

__global__ void k_scatter(const void* __restrict__ ei) {
    int e = blockIdx.x * blockDim.x + threadIdx.x;
    if (e >= EE) return;
    int s, d;
    if (g_is64) {
        s = (int)((const long long*)ei)[e];
        d = (int)((const long long*)ei)[(long long)EE + e];
    } else {
        s = ((const int*)ei)[e];
        d = ((const int*)ei)[EE + e];
    }
    int pos = atomicAdd(&d_cursor[d], 1);
    d_csr[pos] = make_float2(__int_as_float(s), d_dis[s] * d_dis[d]);
}

// ---------------- layer 0: hw = X @ W_in, acc = hw * dis2 --------------------
__global__ __launch_bounds__(256) void k_xw(const float* __restrict__ x,
                                            const float* __restrict__ w,
                                            float4* __restrict__ hw,
                                            float4* __restrict__ acc) {
    __shared__ float  xs[256 * 33];
    __shared__ float4 ws4[FF * 4];
    int tid = threadIdx.x;
    int base = blockIdx.x * 256;

    const float4* wv = (const float4*)w;
    for (int i = tid; i < FF * 4; i += 256) ws4[i] = wv[i];

    int cg = tid & 3;
    int g  = tid >> 2;
    float4 o[4];
    #pragma unroll
    for (int i = 0; i < 4; i++) o[i] = make_float4(0.f, 0.f, 0.f, 0.f);

    for (int kc = 0; kc < 4; kc++) {
        __syncthreads();
        for (int i = tid; i < 256 * 32; i += 256) {
            int r = i >> 5, c = i & 31;
            int n = base + r;
            xs[r * 33 + c] = (n < NN) ? x[n * FF + kc * 32 + c] : 0.f;
        }
        __syncthreads();
        #pragma unroll
        for (int kk = 0; kk < 32; kk++) {
            int k = kc * 32 + kk;
            float4 w4 = ws4[k * 4 + cg];
            #pragma unroll
            for (int i = 0; i < 4; i++) {
                float xv = xs[(g * 4 + i) * 33 + kk];
                o[i].x = fmaf(xv, w4.x, o[i].x);
                o[i].y = fmaf(xv, w4.y, o[i].y);
                o[i].z = fmaf(xv, w4.z, o[i].z);
                o[i].w = fmaf(xv, w4.w, o[i].w);
            }
        }
    }
    #pragma unroll
    for (int i = 0; i < 4; i++) {
        int n = base + g * 4 + i;
        if (n < NN) {
            hw[n * 4 + cg] = o[i];
            float s2 = d_dis2[n];
            acc[n * 4 + cg] = make_float4(o[i].x * s2, o[i].y * s2,
                                          o[i].z * s2, o[i].w * s2);
        }
    }
}

// ---------------- SpMM row accumulation (quad-per-node) ----------------------
// Thread quarter q of node n: accumulates 4 floats. Gathers of the 4 threads
// in a quad hit the SAME 64B-aligned src row -> one 128B line per edge.
__device__ __forceinline__ float4 accum_row(const float4* __restrict__ hw,
                                            const float4* __restrict__ acc,
                                            int n, int q) {
    int start = d_rowptr[n];
    int end   = start + d_cnt[n];
    float4 a = acc[n * 4 + q];           // preinit = self-loop term
    int j = start;
    for (; j + 2 <= end; j += 2) {
        float2 p0 = d_csr[j];
        float2 p1 = d_csr[j + 1];
        float4 v0 = __ldg(hw + __float_as_int(p0.x) * 4 + q);
        float4 v1 = __ldg(hw + __float_as_int(p1.x) * 4 + q);
        a.x = fmaf(p0.y, v0.x, a.x); a.y = fmaf(p0.y, v0.y, a.y);
        a.z = fmaf(p0.y, v0.z, a.z); a.w = fmaf(p0.y, v0.w, a.w);
        a.x = fmaf(p1.y, v1.x, a.x); a.y = fmaf(p1.y, v1.y, a.y);
        a.z = fmaf(p1.y, v1.z, a.z); a.w = fmaf(p1.y, v1.w, a.w);
    }
    if (j < end) {
        float2 p = d_csr[j];
        float4 v = __ldg(hw + __float_as_int(p.x) * 4 + q);
        a.x = fmaf(p.y, v.x, a.x); a.y = fmaf(p.y, v.y, a.y);
        a.z = fmaf(p.y, v.z, a.z); a.w = fmaf(p.y, v.w, a.w);
    }
    return a;
}

// SpMM + fused epilogue: h = relu(agg + bias); hw_out = h @ W;
// acc <- hw_out * dis2 (self-term preinit for the NEXT layer).
__global__ __launch_bounds__(256) void k_spmm_tr(const float4* __restrict__ hw,
                                                 float4* __restrict__ acc,
                                                 const float* __restrict__ bias,
                                                 const float* __restrict__ W,
                                                 float4* __restrict__ hw_out) {
    __shared__ float4 ws4[64];
    __shared__ float  bs[16];
    int tid = threadIdx.x;
    if (tid < 64) ws4[tid] = ((const float4*)W)[tid];
    if (tid < 16) bs[tid] = bias[tid];
    __syncthreads();

    int n = blockIdx.x * 64 + (tid >> 2);     // grid covers NN exactly
    int q = tid & 3;
    float4 a = accum_row(hw, acc, n, q);

    float hq[4];
    hq[0] = fmaxf(a.x + bs[q * 4 + 0], 0.f);
    hq[1] = fmaxf(a.y + bs[q * 4 + 1], 0.f);
    hq[2] = fmaxf(a.z + bs[q * 4 + 2], 0.f);
    hq[3] = fmaxf(a.w + bs[q * 4 + 3], 0.f);

    int lane = tid & 31;
    int qb = lane & ~3;
    float4 o = make_float4(0.f, 0.f, 0.f, 0.f);
    #pragma unroll
    for (int k = 0; k < 16; k++) {
        float hk = __shfl_sync(0xffffffffu, hq[k & 3], qb + (k >> 2));
        float4 w4 = ws4[k * 4 + q];
        o.x = fmaf(hk, w4.x, o.x);
        o.y = fmaf(hk, w4.y, o.y);
        o.z = fmaf(hk, w4.z, o.z);
        o.w = fmaf(hk, w4.w, o.w);
    }
    hw_out[n * 4 + q] = o;
    float s2 = d_dis2[n];
    acc[n * 4 + q] = make_float4(o.x * s2, o.y * s2, o.z * s2, o.w * s2);
}

// SpMM + relu only (identity W: output layer uses post-multiplication)
__global__ __launch_bounds__(256) void k_spmm_relu(const float4* __restrict__ hw,
                                                   float4* __restrict__ acc,
                                                   const float* __restrict__ bias,
                                                   float4* __restrict__ hw_out) {
    __shared__ float bs[16];
    int tid = threadIdx.x;
    if (tid < 16) bs[tid] = bias[tid];
    __syncthreads();

    int n = blockIdx.x * 64 + (tid >> 2);
    int q = tid & 3;
    float4 a = accum_row(hw, acc, n, q);

    float4 h;
    h.x = fmaxf(a.x + bs[q * 4 + 0], 0.f);
    h.y = fmaxf(a.y + bs[q * 4 + 1], 0.f);
    h.z = fmaxf(a.z + bs[q * 4 + 2], 0.f);
    h.w = fmaxf(a.w + bs[q * 4 + 3], 0.f);
    hw_out[n * 4 + q] = h;
    float s2 = d_dis2[n];
    acc[n * 4 + q] = make_float4(h.x * s2, h.y * s2, h.z * s2, h.w * s2);
}

// final SpMM + fused (agg @ W_out + b_out) + log_softmax
__global__ __launch_bounds__(256) void k_spmm_out(const float4* __restrict__ hw,
                                                  const float4* __restrict__ acc,
                                                  const float* __restrict__ W,
                                                  const float* __restrict__ bias,
                                                  float* __restrict__ out) {
    __shared__ float ws[16 * 40];
    __shared__ float bo[40];
    int tid = threadIdx.x;
    for (int i = tid; i < 16 * 40; i += 256) ws[i] = W[i];
    if (tid < 40) bo[tid] = bias[tid];
    __syncthreads();

    int n = blockIdx.x * 64 + (tid >> 2);
    int q = tid & 3;
    float4 a = accum_row(hw, acc, n, q);
    float hq[4] = {a.x, a.y, a.z, a.w};

    int lane = tid & 31;
    int qb = lane & ~3;

    float z[10];
    #pragma unroll
    for (int j = 0; j < 10; j++) z[j] = bo[j * 4 + q];
    #pragma unroll
    for (int k = 0; k < 16; k++) {
        float hk = __shfl_sync(0xffffffffu, hq[k & 3], qb + (k >> 2));
        #pragma unroll
        for (int j = 0; j < 10; j++) {
            z[j] = fmaf(hk, ws[k * 40 + j * 4 + q], z[j]);
        }
    }
    float m = z[0];
    #pragma unroll
    for (int j = 1; j < 10; j++) m = fmaxf(m, z[j]);
    m = fmaxf(m, __shfl_xor_sync(0xffffffffu, m, 1));
    m = fmaxf(m, __shfl_xor_sync(0xffffffffu, m, 2));
    float ssum = 0.f;
    #pragma unroll
    for (int j = 0; j < 10; j++) ssum += __expf(z[j] - m);
    ssum += __shfl_xor_sync(0xffffffffu, ssum, 1);
    ssum += __shfl_xor_sync(0xffffffffu, ssum, 2);
    float lse = m + logf(ssum);
    #pragma unroll
    for (int j = 0; j < 10; j++) {
        out[n * 40 + j * 4 + q] = z[j] - lse;
    }
}

// ---------------- launch ------------------------------------------------------

extern "C" void kernel_launch(void* const* d_in, const int* in_sizes, int n_in,
                              void* d_out, int out_size) {
    const float* x     = (const float*)d_in[0];
    const float* w_in  = (const float*)d_in[1];
    const float* b_in  = (const float*)d_in[2];
    const float* w_hid = (const float*)d_in[3];
    const float* b_hid = (const float*)d_in[4];
    const float* w_out = (const float*)d_in[5];
    const float* b_out = (const float*)d_in[6];
    const void*  ei    = d_in[7];
    float* outp = (float*)d_out;

    float4* bufA; cudaGetSymbolAddress((void**)&bufA, d_bufA);
    float4* bufB; cudaGetSymbolAddress((void**)&bufB, d_bufB);
    float4* bufC; cudaGetSymbolAddress((void**)&bufC, d_bufC);

    const int GB_N = (NN + 255) / 256;
    const int GB_E = (EE + 255) / 256;
    const int GS   = NN / 64;            // 3125, exact

    // prep
    k_init<<<GB_N, 256>>>((const int*)ei);
    k_count<<<GB_E, 256>>>(ei);
    k_scan1<<<NBLK, 1024>>>();
    k_scan2<<<1, 32>>>();
    k_scan3<<<GB_N, 256>>>();
    k_scatter<<<GB_E, 256>>>(ei);

    // layer 0 dense
    k_xw<<<GB_N, 256>>>(x, w_in, bufA, bufB);

    // 8 fused SpMM+transform layers (hw ping-pongs A<->C, acc stays in B)
    float4* cur = bufA;
    float4* nxt = bufC;
    for (int i = 0; i < 8; i++) {
        const float* bias = (i == 0) ? b_in : (b_hid + (i - 1) * HH);
        k_spmm_tr<<<GS, 256>>>(cur, bufB, bias, w_hid + i * HH * HH, nxt);
        float4* t = cur; cur = nxt; nxt = t;
    }

    // SpMM + relu (pre-output), then final SpMM + W_out + log_softmax
    k_spmm_relu<<<GS, 256>>>(cur, bufB, b_hid + 7 * HH, nxt);
    { float4* t = cur; cur = nxt; nxt = t; }
    k_spmm_out<<<GS, 256>>>(cur, bufB, w_out, b_out, outp);
}

// round 3
// speedup vs baseline: 2.3625x; 1.3102x over previous
#include <cuda_runtime.h>
#include <cuda_fp16.h>

#define NN 200000
#define EE 6400000
#define FF 128
#define HH 16
#define NBLK 196   // ceil(NN/1024)

// ---------------- device scratch -------------------------------------------
__device__ int     g_is64;
__device__ int     d_cnt[NN];
__device__ int     d_rowptr[NN];
__device__ int     d_cursor[NN];
__device__ int     d_bsum[NBLK];
__device__ float   d_dis[NN];
__device__ int     d_srcs[EE];        // CSR column indices (dst-sorted)
__device__ uint2   d_hwsA[NN * 4];    // fp16x4 per thread-quarter: dis[n]*hw[n]
__device__ uint2   d_hwsB[NN * 4];

// ---------------- fp16 pack/unpack helpers -----------------------------------
__device__ __forceinline__ float4 h4_to_f4(uint2 u) {
    __half2 a = *reinterpret_cast<__half2*>(&u.x);
    __half2 b = *reinterpret_cast<__half2*>(&u.y);
    float2 fa = __half22float2(a);
    float2 fb = __half22float2(b);
    return make_float4(fa.x, fa.y, fb.x, fb.y);
}
__device__ __forceinline__ uint2 f4_to_h4(float4 f) {
    __half2 a = __floats2half2_rn(f.x, f.y);
    __half2 b = __floats2half2_rn(f.z, f.w);
    uint2 u;
    u.x = *reinterpret_cast<unsigned*>(&a);
    u.y = *reinterpret_cast<unsigned*>(&b);
    return u;
}

// ---------------- prep -------------------------------------------------------

__global__ void k_init(const int* __restrict__ ei) {
    int i = blockIdx.x * blockDim.x + threadIdx.x;
    if (i < NN) d_cnt[i] = 0;
    if (blockIdx.x == 0) {
        if (threadIdx.x == 0) g_is64 = 1;
        __syncthreads();
        if (ei[2 * threadIdx.x + 1] != 0) g_is64 = 0;
    }
}

__global__ void k_count(const void* __restrict__ ei) {
    int e = blockIdx.x * blockDim.x + threadIdx.x;
    if (e >= EE) return;
    int d;
    if (g_is64) d = (int)((const long long*)ei)[(long long)EE + e];
    else        d = ((const int*)ei)[EE + e];
    atomicAdd(&d_cnt[d], 1);
}

// block scan of cnt (exclusive) + fused dis computation
__global__ void k_scan1() {
    __shared__ int sh[1024];
    int tid = threadIdx.x;
    int i = blockIdx.x * 1024 + tid;
    int v = (i < NN) ? d_cnt[i] : 0;
    if (i < NN) d_dis[i] = rsqrtf((float)(v + 1));
    sh[tid] = v;
    __syncthreads();
    for (int off = 1; off < 1024; off <<= 1) {
        int t = 0;
        if (tid >= off) t = sh[tid - off];
        __syncthreads();
        sh[tid] += t;
        __syncthreads();
    }
    if (i < NN) d_rowptr[i] = sh[tid] - v;
    if (tid == 1023) d_bsum[blockIdx.x] = sh[1023];
}

// parallel scan of the 196 block sums (one block)
__global__ void k_scan2() {
    __shared__ int sh[256];
    int tid = threadIdx.x;
    int v = (tid < NBLK) ? d_bsum[tid] : 0;
    sh[tid] = v;
    __syncthreads();
    for (int off = 1; off < 256; off <<= 1) {
        int t = 0;
        if (tid >= off) t = sh[tid - off];
        __syncthreads();
        sh[tid] += t;
        __syncthreads();
    }
    if (tid < NBLK) d_bsum[tid] = sh[tid] - v;   // exclusive
}

__global__ void k_scan3() {
    int i = blockIdx.x * blockDim.x + threadIdx.x;
    if (i >= NN) return;
    int r = d_rowptr[i] + d_bsum[i >> 10];
    d_rowptr[i] = r;
    d_cursor[i] = r;
}

__global__ void k_scatter(const void* __restrict__ ei) {
    int e = blockIdx.x * blockDim.x + threadIdx.x;
    if (e >= EE) return;
    int s, d;
    if (g_is64) {
        s = (int)((const long long*)ei)[e];
        d = (int)((const long long*)ei)[(long long)EE + e];
    } else {
        s = ((const int*)ei)[e];
        d = ((const int*)ei)[EE + e];
    }
    int pos = atomicAdd(&d_cursor[d], 1);
    d_srcs[pos] = s;
}

// ---------------- layer 0: hws = fp16(dis[n] * (X @ W_in)) -------------------
__global__ __launch_bounds__(256) void k_xw(const float* __restrict__ x,
                                            const float* __restrict__ w,
                                            uint2* __restrict__ hws) {
    __shared__ float  xs[256 * 33];
    __shared__ float4 ws4[FF * 4];
    int tid = threadIdx.x;
    int base = blockIdx.x * 256;

    const float4* wv = (const float4*)w;
    for (int i = tid; i < FF * 4; i += 256) ws4[i] = wv[i];

    int cg = tid & 3;
    int g  = tid >> 2;
    float4 o[4];
    #pragma unroll
    for (int i = 0; i < 4; i++) o[i] = make_float4(0.f, 0.f, 0.f, 0.f);

    for (int kc = 0; kc < 4; kc++) {
        __syncthreads();
        for (int i = tid; i < 256 * 32; i += 256) {
            int r = i >> 5, c = i & 31;
            int n = base + r;
            xs[r * 33 + c] = (n < NN) ? x[n * FF + kc * 32 + c] : 0.f;
        }
        __syncthreads();
        #pragma unroll
        for (int kk = 0; kk < 32; kk++) {
            int k = kc * 32 + kk;
            float4 w4 = ws4[k * 4 + cg];
            #pragma unroll
            for (int i = 0; i < 4; i++) {
                float xv = xs[(g * 4 + i) * 33 + kk];
                o[i].x = fmaf(xv, w4.x, o[i].x);
                o[i].y = fmaf(xv, w4.y, o[i].y);
                o[i].z = fmaf(xv, w4.z, o[i].z);
                o[i].w = fmaf(xv, w4.w, o[i].w);
            }
        }
    }
    #pragma unroll
    for (int i = 0; i < 4; i++) {
        int n = base + g * 4 + i;
        if (n < NN) {
            float ds = d_dis[n];
            hws[n * 4 + cg] = f4_to_h4(make_float4(o[i].x * ds, o[i].y * ds,
                                                   o[i].z * ds, o[i].w * ds));
        }
    }
}

// ---------------- SpMM row accumulation (quad-per-node, fp16 payload) --------
// agg(n) = dis[n] * ( sum_{s in N(n)} hws[s] + hws[n] )
__device__ __forceinline__ float4 accum_row(const uint2* __restrict__ hws,
                                            int n, int q, float ds) {
    int start = d_rowptr[n];
    int end   = start + d_cnt[n];
    float4 s0 = h4_to_f4(__ldg(hws + n * 4 + q));     // self term
    float4 s1 = make_float4(0.f, 0.f, 0.f, 0.f);
    int j = start;
    for (; j + 4 <= end; j += 4) {
        int i0 = __ldg(d_srcs + j);
        int i1 = __ldg(d_srcs + j + 1);
        int i2 = __ldg(d_srcs + j + 2);
        int i3 = __ldg(d_srcs + j + 3);
        float4 v0 = h4_to_f4(__ldg(hws + i0 * 4 + q));
        float4 v1 = h4_to_f4(__ldg(hws + i1 * 4 + q));
        float4 v2 = h4_to_f4(__ldg(hws + i2 * 4 + q));
        float4 v3 = h4_to_f4(__ldg(hws + i3 * 4 + q));
        s0.x += v0.x; s0.y += v0.y; s0.z += v0.z; s0.w += v0.w;
        s1.x += v1.x; s1.y += v1.y; s1.z += v1.z; s1.w += v1.w;
        s0.x += v2.x; s0.y += v2.y; s0.z += v2.z; s0.w += v2.w;
        s1.x += v3.x; s1.y += v3.y; s1.z += v3.z; s1.w += v3.w;
    }
    for (; j < end; j++) {
        int i0 = __ldg(d_srcs + j);
        float4 v = h4_to_f4(__ldg(hws + i0 * 4 + q));
        s0.x += v.x; s0.y += v.y; s0.z += v.z; s0.w += v.w;
    }
    return make_float4(ds * (s0.x + s1.x), ds * (s0.y + s1.y),
                       ds * (s0.z + s1.z), ds * (s0.w + s1.w));
}

// SpMM + fused epilogue: h = relu(agg + bias); o = h @ W;
// hws_out = fp16(dis[n] * o)
__global__ __launch_bounds__(256) void k_spmm_tr(const uint2* __restrict__ hws,
                                                 const float* __restrict__ bias,
                                                 const float* __restrict__ W,
                                                 uint2* __restrict__ hws_out) {
    __shared__ float4 ws4[64];
    __shared__ float  bs[16];
    int tid = threadIdx.x;
    if (tid < 64) ws4[tid] = ((const float4*)W)[tid];
    if (tid < 16) bs[tid] = bias[tid];
    __syncthreads();

    int n = blockIdx.x * 64 + (tid >> 2);
    int q = tid & 3;
    float ds = __ldg(d_dis + n);
    float4 a = accum_row(hws, n, q, ds);

    float hq[4];
    hq[0] = fmaxf(a.x + bs[q * 4 + 0], 0.f);
    hq[1] = fmaxf(a.y + bs[q * 4 + 1], 0.f);
    hq[2] = fmaxf(a.z + bs[q * 4 + 2], 0.f);
    hq[3] = fmaxf(a.w + bs[q * 4 + 3], 0.f);

    int lane = tid & 31;
    int qb = lane & ~3;
    float4 o = make_float4(0.f, 0.f, 0.f, 0.f);
    #pragma unroll
    for (int k = 0; k < 16; k++) {
        float hk = __shfl_sync(0xffffffffu, hq[k & 3], qb + (k >> 2));
        float4 w4 = ws4[k * 4 + q];
        o.x = fmaf(hk, w4.x, o.x);
        o.y = fmaf(hk, w4.y, o.y);
        o.z = fmaf(hk, w4.z, o.z);
        o.w = fmaf(hk, w4.w, o.w);
    }
    hws_out[n * 4 + q] = f4_to_h4(make_float4(o.x * ds, o.y * ds,
                                              o.z * ds, o.w * ds));
}

// SpMM + relu only (before the output-layer aggregation)
__global__ __launch_bounds__(256) void k_spmm_relu(const uint2* __restrict__ hws,
                                                   const float* __restrict__ bias,
                                                   uint2* __restrict__ hws_out) {
    __shared__ float bs[16];
    int tid = threadIdx.x;
    if (tid < 16) bs[tid] = bias[tid];
    __syncthreads();

    int n = blockIdx.x * 64 + (tid >> 2);
    int q = tid & 3;
    float ds = __ldg(d_dis + n);
    float4 a = accum_row(hws, n, q, ds);

    float4 h;
    h.x = fmaxf(a.x + bs[q * 4 + 0], 0.f) * ds;
    h.y = fmaxf(a.y + bs[q * 4 + 1], 0.f) * ds;
    h.z = fmaxf(a.z + bs[q * 4 + 2], 0.f) * ds;
    h.w = fmaxf(a.w + bs[q * 4 + 3], 0.f) * ds;
    hws_out[n * 4 + q] = f4_to_h4(h);
}

// final SpMM + fused (agg @ W_out + b_out) + log_softmax
__global__ __launch_bounds__(256) void k_spmm_out(const uint2* __restrict__ hws,
                                                  const float* __restrict__ W,
                                                  const float* __restrict__ bias,
                                                  float* __restrict__ out) {
    __shared__ float ws[16 * 40];
    __shared__ float bo[40];
    int tid = threadIdx.x;
    for (int i = tid; i < 16 * 40; i += 256) ws[i] = W[i];
    if (tid < 40) bo[tid] = bias[tid];
    __syncthreads();

    int n = blockIdx.x * 64 + (tid >> 2);
    int q = tid & 3;
    float ds = __ldg(d_dis + n);
    float4 a = accum_row(hws, n, q, ds);
    float hq[4] = {a.x, a.y, a.z, a.w};

    int lane = tid & 31;
    int qb = lane & ~3;

    float z[10];
    #pragma unroll
    for (int j = 0; j < 10; j++) z[j] = bo[j * 4 + q];
    #pragma unroll
    for (int k = 0; k < 16; k++) {
        float hk = __shfl_sync(0xffffffffu, hq[k & 3], qb + (k >> 2));
        #pragma unroll
        for (int j = 0; j < 10; j++) {
            z[j] = fmaf(hk, ws[k * 40 + j * 4 + q], z[j]);
        }
    }
    float m = z[0];
    #pragma unroll
    for (int j = 1; j < 10; j++) m = fmaxf(m, z[j]);
    m = fmaxf(m, __shfl_xor_sync(0xffffffffu, m, 1));
    m = fmaxf(m, __shfl_xor_sync(0xffffffffu, m, 2));
    float ssum = 0.f;
    #pragma unroll
    for (int j = 0; j < 10; j++) ssum += __expf(z[j] - m);
    ssum += __shfl_xor_sync(0xffffffffu, ssum, 1);
    ssum += __shfl_xor_sync(0xffffffffu, ssum, 2);
    float lse = m + logf(ssum);
    #pragma unroll
    for (int j = 0; j < 10; j++) {
        out[n * 40 + j * 4 + q] = z[j] - lse;
    }
}

// ---------------- launch ------------------------------------------------------

extern "C" void kernel_launch(void* const* d_in, const int* in_sizes, int n_in,
                              void* d_out, int out_size) {
    const float* x     = (const float*)d_in[0];
    const float* w_in  = (const float*)d_in[1];
    const float* b_in  = (const float*)d_in[2];
    const float* w_hid = (const float*)d_in[3];
    const float* b_hid = (const float*)d_in[4];
    const float* w_out = (const float*)d_in[5];
    const float* b_out = (const float*)d_in[6];
    const void*  ei    = d_in[7];
    float* outp = (float*)d_out;

    uint2* bufA; cudaGetSymbolAddress((void**)&bufA, d_hwsA);
    uint2* bufB; cudaGetSymbolAddress((void**)&bufB, d_hwsB);

    const int GB_N = (NN + 255) / 256;
    const int GB_E = (EE + 255) / 256;
    const int GS   = NN / 64;            // 3125, exact

    // prep
    k_init<<<GB_N, 256>>>((const int*)ei);
    k_count<<<GB_E, 256>>>(ei);
    k_scan1<<<NBLK, 1024>>>();
    k_scan2<<<1, 256>>>();
    k_scan3<<<GB_N, 256>>>();
    k_scatter<<<GB_E, 256>>>(ei);

    // layer 0 dense
    k_xw<<<GB_N, 256>>>(x, w_in, bufA);

    // 8 fused SpMM+transform layers (ping-pong A<->B)
    uint2* cur = bufA;
    uint2* nxt = bufB;
    for (int i = 0; i < 8; i++) {
        const float* bias = (i == 0) ? b_in : (b_hid + (i - 1) * HH);
        k_spmm_tr<<<GS, 256>>>(cur, bias, w_hid + i * HH * HH, nxt);
        uint2* t = cur; cur = nxt; nxt = t;
    }

    // SpMM + relu (pre-output), then final SpMM + W_out + log_softmax
    k_spmm_relu<<<GS, 256>>>(cur, b_hid + 7 * HH, nxt);
    { uint2* t = cur; cur = nxt; nxt = t; }
    k_spmm_out<<<GS, 256>>>(cur, w_out, b_out, outp);
}